// round 2
// baseline (speedup 1.0000x reference)
#include <cuda_runtime.h>
#include <cuda_bf16.h>

#define B_      512
#define GFS_    512
#define NATOMS_ 128
#define KATT_   256

// scratch for m_gate (no cudaMalloc allowed)
__device__ float g_mgate[B_ * KATT_];

// ---------------------------------------------------------------------------
// MUFU-free tanh. abs err ~2e-7.
//  |x| < 0.55 : odd Taylor to x^13
//  |x| >= 0.55: tanh = 1 - 2u/(1+u), u = exp(-2|x|) via FMA exp2 + Newton recip
// ---------------------------------------------------------------------------
__device__ __forceinline__ float fast_tanh(float x) {
    float a = fabsf(x);
    if (a < 0.55f) {
        float s = x * x;
        float p = 3.5920885e-3f;
        p = fmaf(p, s, -8.8631962e-3f);
        p = fmaf(p, s,  2.1869488e-2f);
        p = fmaf(p, s, -5.3968254e-2f);
        p = fmaf(p, s,  1.3333334e-1f);
        p = fmaf(p, s, -3.3333334e-1f);
        p = fmaf(p, s,  1.0f);
        return x * p;
    } else {
        float am = fminf(a, 15.0f);
        float t  = am * (-2.885390082f);          // -2*log2(e)*a
        float big = t + 12582912.0f;              // round-to-nearest via 1.5*2^23
        float nf  = big - 12582912.0f;
        float f   = t - nf;                       // f in [-0.5, 0.5]
        int ni    = __float_as_int(big) - 0x4B400000;
        float p = 1.5403530e-4f;                  // exp2(f) Taylor, rel err ~1.2e-7
        p = fmaf(p, f, 1.3333558e-3f);
        p = fmaf(p, f, 9.6181291e-3f);
        p = fmaf(p, f, 5.5504109e-2f);
        p = fmaf(p, f, 2.4022651e-1f);
        p = fmaf(p, f, 6.9314718e-1f);
        p = fmaf(p, f, 1.0f);
        float u = p * __int_as_float((ni + 127) << 23);   // u = exp(-2a) in (0, 0.333]
        float d = 1.0f + u;
        float q = 1.0f - u;                       // seed for 1/(1+u): 1-u+u^2-u^3
        q = fmaf(-u, q, 1.0f);
        q = fmaf(-u, q, 1.0f);
        q = q * fmaf(-d, q, 2.0f);                // Newton x2
        q = q * fmaf(-d, q, 2.0f);
        float r = fmaf(-2.0f * u, q, 1.0f);
        return copysignf(r, x);
    }
}

// ---------------------------------------------------------------------------
// K1: per-batch  M_0 = tanh(sumN(V)/64)*tanh(sumN(Q)/64);  m_gate = tanh(W_m M_0)
// grid = B, block = 256
// ---------------------------------------------------------------------------
__global__ __launch_bounds__(256) void gate_kernel(
    const float* __restrict__ V, const float* __restrict__ Q,
    const float* __restrict__ Wm)
{
    int b    = blockIdx.x;
    int tid  = threadIdx.x;
    int lane = tid & 31;
    int warp = tid >> 5;

    __shared__ __align__(16) float sM0[GFS_];

    const float4* Vb = (const float4*)(V + (size_t)b * GFS_ * NATOMS_);
    const float4* Qb = (const float4*)(Q + (size_t)b * GFS_ * NATOMS_);

    for (int f = warp; f < GFS_; f += 8) {
        float4 v = Vb[f * 32 + lane];
        float4 q = Qb[f * 32 + lane];
        float sv = v.x + v.y + v.z + v.w;
        float sq = q.x + q.y + q.z + q.w;
        #pragma unroll
        for (int off = 16; off; off >>= 1) {
            sv += __shfl_xor_sync(0xffffffffu, sv, off);
            sq += __shfl_xor_sync(0xffffffffu, sq, off);
        }
        if (lane == 0)
            sM0[f] = fast_tanh(sv * (1.0f / 64.0f)) * fast_tanh(sq * (1.0f / 64.0f));
    }
    __syncthreads();

    // m_gate: one k per thread (K=256)
    int k = tid;
    const float4* wr = (const float4*)(Wm + (size_t)k * GFS_);
    const float4* m4 = (const float4*)sM0;
    float acc = 0.0f;
    #pragma unroll 8
    for (int i = 0; i < GFS_ / 4; i++) {
        float4 w = wr[i];
        float4 m = m4[i];
        acc = fmaf(w.x, m.x, acc);
        acc = fmaf(w.y, m.y, acc);
        acc = fmaf(w.z, m.z, acc);
        acc = fmaf(w.w, m.w, acc);
    }
    g_mgate[b * KATT_ + k] = fast_tanh(acc);
}

// ---------------------------------------------------------------------------
// K2: per (b, src): T = W_x @ X[b]  (256x128, K=512);
//     s[n] = sum_k Wh[k]*g[k]*tanh(T[k,n]); softmax -> alpha; vector = X @ alpha
// grid = (B, 2), block = 512
// ---------------------------------------------------------------------------
__global__ __launch_bounds__(512, 1) void main_kernel(
    const float* __restrict__ V, const float* __restrict__ Q,
    const float* __restrict__ Wv, const float* __restrict__ Wq,
    const float* __restrict__ Wh, float* __restrict__ out)
{
    int b   = blockIdx.x;
    int src = blockIdx.y;

    const float* X = (src == 0 ? V : Q) + (size_t)b * GFS_ * NATOMS_;
    const float* W = (src == 0 ? Wv : Wq);

    __shared__ __align__(16) float As[16 * 260];   // W tile, [f][k], padded
    __shared__ __align__(16) float Bs[16 * 132];   // X tile, [f][n], padded
    __shared__ float whg[KATT_];
    __shared__ float sred[128];
    __shared__ __align__(16) float alpha[128];

    int tid = threadIdx.x;
    if (tid < KATT_) whg[tid] = Wh[tid] * g_mgate[b * KATT_ + tid];

    int ty = tid >> 4;          // 0..31 -> k rows
    int tx = tid & 15;          // 0..15 -> n cols
    int kb = ty * 8;
    int nb = tx * 8;

    float acc[8][8];
    #pragma unroll
    for (int i = 0; i < 8; i++)
        #pragma unroll
        for (int j = 0; j < 8; j++) acc[i][j] = 0.0f;

    for (int f0 = 0; f0 < GFS_; f0 += 16) {
        // A tile: As[fi][k] = W[k][f0+fi]
        #pragma unroll
        for (int it = 0; it < 2; it++) {
            int q4  = it * 512 + tid;          // 1024 float4
            int k   = q4 >> 2;
            int fi4 = (q4 & 3) << 2;
            float4 w = *(const float4*)(W + (size_t)k * GFS_ + f0 + fi4);
            As[(fi4 + 0) * 260 + k] = w.x;
            As[(fi4 + 1) * 260 + k] = w.y;
            As[(fi4 + 2) * 260 + k] = w.z;
            As[(fi4 + 3) * 260 + k] = w.w;
        }
        // B tile: Bs[fi][c] = X[f0+fi][c]  (coalesced float4)
        {
            int fi = tid >> 5;
            int c4 = (tid & 31) << 2;
            *(float4*)&Bs[fi * 132 + c4] =
                *(const float4*)(X + (size_t)(f0 + fi) * NATOMS_ + c4);
        }
        __syncthreads();
        #pragma unroll
        for (int f = 0; f < 16; f++) {
            float4 a0 = *(float4*)&As[f * 260 + kb];
            float4 a1 = *(float4*)&As[f * 260 + kb + 4];
            float4 b0 = *(float4*)&Bs[f * 132 + nb];
            float4 b1 = *(float4*)&Bs[f * 132 + nb + 4];
            float av[8] = {a0.x, a0.y, a0.z, a0.w, a1.x, a1.y, a1.z, a1.w};
            float bv[8] = {b0.x, b0.y, b0.z, b0.w, b1.x, b1.y, b1.z, b1.w};
            #pragma unroll
            for (int i = 0; i < 8; i++)
                #pragma unroll
                for (int j = 0; j < 8; j++)
                    acc[i][j] = fmaf(av[i], bv[j], acc[i][j]);
        }
        __syncthreads();
    }

    // Epilogue: s[n] = sum_k whg[k] * tanh(T[k,n]); reduce over ty via smem.
    float* red = As;            // reuse As (4160 floats >= 32*128)
    #pragma unroll
    for (int j = 0; j < 8; j++) {
        float p = 0.0f;
        #pragma unroll
        for (int i = 0; i < 8; i++)
            p = fmaf(whg[kb + i], fast_tanh(acc[i][j]), p);
        red[ty * 128 + nb + j] = p;
    }
    __syncthreads();

    if (tid < 128) {
        float sv = 0.0f;
        #pragma unroll 8
        for (int t = 0; t < 32; t++) sv += red[t * 128 + tid];
        alpha[tid] = sv;        // keep raw logits
        sred[tid]  = sv;        // reduce copy
    }
    __syncthreads();
    // max reduce
    #pragma unroll
    for (int off = 64; off; off >>= 1) {
        if (tid < off) sred[tid] = fmaxf(sred[tid], sred[tid + off]);
        __syncthreads();
    }
    float mx = sred[0];
    __syncthreads();
    if (tid < 128) {
        float e = expf(alpha[tid] - mx);
        alpha[tid] = e;
        sred[tid]  = e;
    }
    __syncthreads();
    #pragma unroll
    for (int off = 64; off; off >>= 1) {
        if (tid < off) sred[tid] += sred[tid + off];
        __syncthreads();
    }
    float rsum = 1.0f / sred[0];
    __syncthreads();
    if (tid < 128) {
        float a = alpha[tid] * rsum;
        alpha[tid] = a;
        // alpha output: after both vector blocks
        out[2 * B_ * GFS_ + src * B_ * NATOMS_ + b * NATOMS_ + tid] = a;
    }
    __syncthreads();

    // vector[f] = sum_n alpha[n] * X[f][n]
    {
        int f = tid;            // 512 threads == GFS
        const float4* xr = (const float4*)(X + (size_t)f * NATOMS_);
        const float4* al = (const float4*)alpha;
        float a = 0.0f;
        #pragma unroll 8
        for (int i = 0; i < 32; i++) {
            float4 v = xr[i];
            float4 w = al[i];
            a = fmaf(v.x, w.x, a);
            a = fmaf(v.y, w.y, a);
            a = fmaf(v.z, w.z, a);
            a = fmaf(v.w, w.w, a);
        }
        out[src * B_ * GFS_ + b * GFS_ + f] = a;
    }
}

extern "C" void kernel_launch(void* const* d_in, const int* in_sizes, int n_in,
                              void* d_out, int out_size)
{
    const float* V  = (const float*)d_in[0];
    const float* Q  = (const float*)d_in[1];
    const float* Wm = (const float*)d_in[2];
    const float* Wv = (const float*)d_in[3];
    const float* Wq = (const float*)d_in[4];
    const float* Wh = (const float*)d_in[5];
    float* out = (float*)d_out;

    gate_kernel<<<B_, 256>>>(V, Q, Wm);
    dim3 grid(B_, 2);
    main_kernel<<<grid, 512>>>(V, Q, Wv, Wq, Wh, out);
}

// round 4
// speedup vs baseline: 2.1129x; 2.1129x over previous
#include <cuda_runtime.h>
#include <cuda_bf16.h>
#include <cstdint>

#define B_      512
#define GFS_    512
#define NATOMS_ 128
#define KATT_   256

// ---------------- scratch (no cudaMalloc allowed) ----------------
__device__ float g_mgate[B_ * KATT_];
__device__ float g_M0[B_ * GFS_];
__device__ __nv_bfloat16 g_wHi[2][KATT_ * GFS_];
__device__ __nv_bfloat16 g_wLo[2][KATT_ * GFS_];

// ---------------- helpers ----------------
__device__ __forceinline__ uint32_t smem_u32(const void* p) {
    uint32_t a;
    asm("{ .reg .u64 t; cvta.to.shared.u64 t, %1; cvt.u32.u64 %0, t; }" : "=r"(a) : "l"(p));
    return a;
}
__device__ __forceinline__ uint32_t sw128(uint32_t off) { return off ^ ((off >> 3) & 0x70); }

__device__ __forceinline__ void ldsm_x4(uint32_t* r, uint32_t addr) {
    asm volatile("ldmatrix.sync.aligned.m8n8.x4.shared.b16 {%0,%1,%2,%3}, [%4];"
                 : "=r"(r[0]), "=r"(r[1]), "=r"(r[2]), "=r"(r[3]) : "r"(addr));
}
__device__ __forceinline__ void mma_bf16(float* c, const uint32_t* a, const uint32_t* b) {
    asm volatile("mma.sync.aligned.m16n8k16.row.col.f32.bf16.bf16.f32 "
                 "{%0,%1,%2,%3}, {%4,%5,%6,%7}, {%8,%9}, {%0,%1,%2,%3};"
                 : "+f"(c[0]), "+f"(c[1]), "+f"(c[2]), "+f"(c[3])
                 : "r"(a[0]), "r"(a[1]), "r"(a[2]), "r"(a[3]), "r"(b[0]), "r"(b[1]));
}
__device__ __forceinline__ void cp16(uint32_t saddr, const void* gaddr) {
    asm volatile("cp.async.cg.shared.global [%0], [%1], 16;" :: "r"(saddr), "l"(gaddr));
}
#define CP_COMMIT() asm volatile("cp.async.commit_group;" ::: "memory")
#define CP_WAIT0()  asm volatile("cp.async.wait_group 0;" ::: "memory")

// ---------------- fast tanh (MUFU-free, abs err ~2e-7) ----------------
__device__ __forceinline__ float fast_tanh(float x) {
    float a = fabsf(x);
    if (a < 0.55f) {
        float s = x * x;
        float p = 3.5920885e-3f;
        p = fmaf(p, s, -8.8631962e-3f);
        p = fmaf(p, s,  2.1869488e-2f);
        p = fmaf(p, s, -5.3968254e-2f);
        p = fmaf(p, s,  1.3333334e-1f);
        p = fmaf(p, s, -3.3333334e-1f);
        p = fmaf(p, s,  1.0f);
        return x * p;
    } else {
        float am = fminf(a, 15.0f);
        float t  = am * (-2.885390082f);
        float big = t + 12582912.0f;
        float nf  = big - 12582912.0f;
        float f   = t - nf;
        int ni    = __float_as_int(big) - 0x4B400000;
        float p = 1.5403530e-4f;
        p = fmaf(p, f, 1.3333558e-3f);
        p = fmaf(p, f, 9.6181291e-3f);
        p = fmaf(p, f, 5.5504109e-2f);
        p = fmaf(p, f, 2.4022651e-1f);
        p = fmaf(p, f, 6.9314718e-1f);
        p = fmaf(p, f, 1.0f);
        float u = p * __int_as_float((ni + 127) << 23);
        float d = 1.0f + u;
        float q = 1.0f - u;
        q = fmaf(-u, q, 1.0f);
        q = fmaf(-u, q, 1.0f);
        q = q * fmaf(-d, q, 2.0f);
        q = q * fmaf(-d, q, 2.0f);
        float r = fmaf(-2.0f * u, q, 1.0f);
        return copysignf(r, x);
    }
}

// ---------------- P0: W -> bf16 hi/lo ----------------
__global__ __launch_bounds__(1024) void prep_kernel(const float* __restrict__ Wv,
                                                    const float* __restrict__ Wq)
{
    int id = blockIdx.x * 1024 + threadIdx.x;
    int src = id >> 17;
    int e   = id & 131071;
    float x = (src ? Wq : Wv)[e];
    __nv_bfloat16 h = __float2bfloat16(x);
    __nv_bfloat16 l = __float2bfloat16(x - __bfloat162float(h));
    g_wHi[src][e] = h;
    g_wLo[src][e] = l;
}

// ---------------- K1a: M0[b][f] = tanh(sumN V/64) * tanh(sumN Q/64) ----------------
__global__ __launch_bounds__(256) void m0_kernel(const float* __restrict__ V,
                                                 const float* __restrict__ Q)
{
    int b    = blockIdx.x >> 2;
    int part = blockIdx.x & 3;
    int lane = threadIdx.x & 31;
    int warp = threadIdx.x >> 5;

    for (int i = 0; i < 16; i++) {
        int f = part * 128 + warp * 16 + i;
        size_t base = ((size_t)b * GFS_ + f) * NATOMS_;
        float4 v = *(const float4*)(V + base + lane * 4);
        float4 q = *(const float4*)(Q + base + lane * 4);
        float sv = v.x + v.y + v.z + v.w;
        float sq = q.x + q.y + q.z + q.w;
        #pragma unroll
        for (int off = 16; off; off >>= 1) {
            sv += __shfl_xor_sync(0xffffffffu, sv, off);
            sq += __shfl_xor_sync(0xffffffffu, sq, off);
        }
        if (lane == 0)
            g_M0[b * GFS_ + f] = fast_tanh(sv * (1.0f / 64.0f)) * fast_tanh(sq * (1.0f / 64.0f));
    }
}

// ---------------- K1b: m_gate = tanh(Wm @ M0), 4 batches per CTA ----------------
__global__ __launch_bounds__(256) void gate_kernel(const float* __restrict__ Wm)
{
    __shared__ __align__(16) float M0s[4][GFS_];
    int b0  = blockIdx.x * 4;
    int tid = threadIdx.x;

    for (int i = tid; i < 4 * GFS_ / 4; i += 256)
        ((float4*)&M0s[0][0])[i] = ((const float4*)(g_M0 + b0 * GFS_))[i];
    __syncthreads();

    int k = tid;
    const float4* wr = (const float4*)(Wm + (size_t)k * GFS_);
    float acc0 = 0.f, acc1 = 0.f, acc2 = 0.f, acc3 = 0.f;
    #pragma unroll 4
    for (int i = 0; i < GFS_ / 4; i++) {
        float4 w = wr[i];
        float4 m0 = ((const float4*)M0s[0])[i];
        float4 m1 = ((const float4*)M0s[1])[i];
        float4 m2 = ((const float4*)M0s[2])[i];
        float4 m3 = ((const float4*)M0s[3])[i];
        acc0 = fmaf(w.x, m0.x, fmaf(w.y, m0.y, fmaf(w.z, m0.z, fmaf(w.w, m0.w, acc0))));
        acc1 = fmaf(w.x, m1.x, fmaf(w.y, m1.y, fmaf(w.z, m1.z, fmaf(w.w, m1.w, acc1))));
        acc2 = fmaf(w.x, m2.x, fmaf(w.y, m2.y, fmaf(w.z, m2.z, fmaf(w.w, m2.w, acc2))));
        acc3 = fmaf(w.x, m3.x, fmaf(w.y, m3.y, fmaf(w.z, m3.z, fmaf(w.w, m3.w, acc3))));
    }
    g_mgate[(b0 + 0) * KATT_ + k] = fast_tanh(acc0);
    g_mgate[(b0 + 1) * KATT_ + k] = fast_tanh(acc1);
    g_mgate[(b0 + 2) * KATT_ + k] = fast_tanh(acc2);
    g_mgate[(b0 + 3) * KATT_ + k] = fast_tanh(acc3);
}

// ---------------- K2: mma.sync main kernel ----------------
#define STAGE_BYTES 98304
#define A_HI_OFF    0
#define A_LO_OFF    32768
#define B_HI_OFF    65536
#define B_LO_OFF    81920
#define WHG_OFF     196608
#define PART_OFF    197632
#define ALPHA_OFF   199680
#define SRED_OFF    200192
#define SMEM_TOTAL  200704

// issue cp.async for A chunk (hi+lo) at feature offset f0 into stage buffer
__device__ __forceinline__ void fillA(char* sm, uint32_t sb, int s, int f0, int tid,
                                      const __nv_bfloat16* WHi, const __nv_bfloat16* WLo)
{
    uint32_t stage = sb + s * STAGE_BYTES;
    #pragma unroll
    for (int it = 0; it < 4; it++) {
        int idx = it * 512 + tid;          // 0..2047
        int m   = idx >> 3;
        int cc  = idx & 7;
        uint32_t soff = sw128((uint32_t)(m * 128 + cc * 16));
        cp16(stage + A_HI_OFF + soff, WHi + (size_t)m * GFS_ + f0 + cc * 8);
        cp16(stage + A_LO_OFF + soff, WLo + (size_t)m * GFS_ + f0 + cc * 8);
    }
}

__device__ __forceinline__ void ldB(float* bx, const float* X, int f0, int tid)
{
    int nB = tid & 127;
    int fq = tid >> 7;
    #pragma unroll
    for (int j = 0; j < 4; j++) {
        int f = f0 + fq * 16 + j * 4;
        bx[j * 4 + 0] = X[(size_t)(f + 0) * NATOMS_ + nB];
        bx[j * 4 + 1] = X[(size_t)(f + 1) * NATOMS_ + nB];
        bx[j * 4 + 2] = X[(size_t)(f + 2) * NATOMS_ + nB];
        bx[j * 4 + 3] = X[(size_t)(f + 3) * NATOMS_ + nB];
    }
}

__device__ __forceinline__ void stB(char* sm, int s, const float* bx, int tid)
{
    int nB = tid & 127;
    int fq = tid >> 7;
    #pragma unroll
    for (int j = 0; j < 4; j++) {
        float x0 = bx[j*4+0], x1 = bx[j*4+1], x2 = bx[j*4+2], x3 = bx[j*4+3];
        __nv_bfloat16 h0 = __float2bfloat16(x0), h1 = __float2bfloat16(x1);
        __nv_bfloat16 h2 = __float2bfloat16(x2), h3 = __float2bfloat16(x3);
        __nv_bfloat162 hA = {h0, h1}, hB = {h2, h3};
        __nv_bfloat162 lA = {__float2bfloat16(x0 - __bfloat162float(h0)),
                             __float2bfloat16(x1 - __bfloat162float(h1))};
        __nv_bfloat162 lB = {__float2bfloat16(x2 - __bfloat162float(h2)),
                             __float2bfloat16(x3 - __bfloat162float(h3))};
        int fl = fq * 16 + j * 4;
        uint32_t soff = sw128((uint32_t)(nB * 128 + fl * 2));
        uint2 uh = { *(uint32_t*)&hA, *(uint32_t*)&hB };
        uint2 ul = { *(uint32_t*)&lA, *(uint32_t*)&lB };
        *(uint2*)(sm + s * STAGE_BYTES + B_HI_OFF + soff) = uh;
        *(uint2*)(sm + s * STAGE_BYTES + B_LO_OFF + soff) = ul;
    }
}

__global__ void __launch_bounds__(512, 1)
main_kernel(const float* __restrict__ V, const float* __restrict__ Q,
            const float* __restrict__ Wh, float* __restrict__ out)
{
    extern __shared__ char sm[];
    uint32_t sb = smem_u32(sm);

    int b   = blockIdx.x;
    int src = blockIdx.y;
    int tid = threadIdx.x;
    int wid = tid >> 5;
    int lane = tid & 31;

    const float* X = (src ? Q : V) + (size_t)b * GFS_ * NATOMS_;
    const __nv_bfloat16* WHi = g_wHi[src];
    const __nv_bfloat16* WLo = g_wLo[src];

    float* whg   = (float*)(sm + WHG_OFF);
    float* part  = (float*)(sm + PART_OFF);
    float* alpha = (float*)(sm + ALPHA_OFF);
    float* sred  = (float*)(sm + SRED_OFF);

    if (tid < KATT_) whg[tid] = Wh[tid] * g_mgate[b * KATT_ + tid];

    // warp tile: 64m x 32n;  4x4 warp grid
    int wm = wid >> 2;
    int wn = wid & 3;

    float acc[4][4][4];
    #pragma unroll
    for (int i = 0; i < 4; i++)
        #pragma unroll
        for (int j = 0; j < 4; j++)
            #pragma unroll
            for (int e = 0; e < 4; e++) acc[i][j][e] = 0.0f;

    // per-lane address components (byte offsets within a tile region)
    uint32_t aRow = (uint32_t)((wm * 64 + (lane & 15)) * 128);
    uint32_t aCol = (uint32_t)((lane >> 4) * 16);
    uint32_t bRow = (uint32_t)((wn * 32 + ((lane >> 4) * 8) + (lane & 7)) * 128);
    uint32_t bCol = (uint32_t)(((lane >> 3) & 1) * 16);

    // prologue: fill chunk 0
    fillA(sm, sb, 0, 0, tid, WHi, WLo);
    CP_COMMIT();
    {
        float bx[16];
        ldB(bx, X, 0, tid);
        stB(sm, 0, bx, tid);
    }
    CP_WAIT0();
    __syncthreads();

    float bx[16];
    #pragma unroll 1
    for (int c = 0; c < 8; c++) {
        int s = c & 1;
        uint32_t stage = sb + s * STAGE_BYTES;

        if (c < 7) {
            fillA(sm, sb, s ^ 1, (c + 1) * 64, tid, WHi, WLo);
            CP_COMMIT();
            ldB(bx, X, (c + 1) * 64, tid);
        }

        uint32_t aHi = stage + A_HI_OFF;
        uint32_t aLo = stage + A_LO_OFF;
        uint32_t bHi = stage + B_HI_OFF;
        uint32_t bLo = stage + B_LO_OFF;

        #pragma unroll
        for (int ks = 0; ks < 4; ks++) {
            uint32_t kOff = (uint32_t)(ks * 32);
            uint32_t a[4][4], bh[4][2], bl[4][2];
            #pragma unroll
            for (int i = 0; i < 4; i++)
                ldsm_x4(a[i], aHi + sw128(aRow + i * 2048 + kOff + aCol));
            #pragma unroll
            for (int jj = 0; jj < 2; jj++) {
                uint32_t r[4];
                ldsm_x4(r, bHi + sw128(bRow + jj * 2048 + kOff + bCol));
                bh[2*jj][0] = r[0]; bh[2*jj][1] = r[1];
                bh[2*jj+1][0] = r[2]; bh[2*jj+1][1] = r[3];
                ldsm_x4(r, bLo + sw128(bRow + jj * 2048 + kOff + bCol));
                bl[2*jj][0] = r[0]; bl[2*jj][1] = r[1];
                bl[2*jj+1][0] = r[2]; bl[2*jj+1][1] = r[3];
            }
            #pragma unroll
            for (int i = 0; i < 4; i++)
                #pragma unroll
                for (int j = 0; j < 4; j++) {
                    mma_bf16(acc[i][j], a[i], bh[j]);   // hh
                    mma_bf16(acc[i][j], a[i], bl[j]);   // hl
                }
            #pragma unroll
            for (int i = 0; i < 4; i++)
                ldsm_x4(a[i], aLo + sw128(aRow + i * 2048 + kOff + aCol));
            #pragma unroll
            for (int i = 0; i < 4; i++)
                #pragma unroll
                for (int j = 0; j < 4; j++)
                    mma_bf16(acc[i][j], a[i], bh[j]);   // lh
        }

        if (c < 7) {
            stB(sm, s ^ 1, bx, tid);
            CP_WAIT0();
        }
        __syncthreads();
    }

    // ---- epilogue: col partials p[j][e] = sum_m whg[m]*tanh(T[m,n]) ----
    float p[4][2];
    #pragma unroll
    for (int j = 0; j < 4; j++) { p[j][0] = 0.f; p[j][1] = 0.f; }

    int m0r = wm * 64 + (lane >> 2);
    #pragma unroll
    for (int i = 0; i < 4; i++) {
        float w0 = whg[m0r + i * 16];
        float w1 = whg[m0r + i * 16 + 8];
        #pragma unroll
        for (int j = 0; j < 4; j++) {
            p[j][0] = fmaf(w0, fast_tanh(acc[i][j][0]), p[j][0]);
            p[j][1] = fmaf(w0, fast_tanh(acc[i][j][1]), p[j][1]);
            p[j][0] = fmaf(w1, fast_tanh(acc[i][j][2]), p[j][0]);
            p[j][1] = fmaf(w1, fast_tanh(acc[i][j][3]), p[j][1]);
        }
    }
    // reduce over lane>>2 (rows) within warp
    #pragma unroll
    for (int off = 4; off <= 16; off <<= 1)
        #pragma unroll
        for (int j = 0; j < 4; j++) {
            p[j][0] += __shfl_xor_sync(0xffffffffu, p[j][0], off);
            p[j][1] += __shfl_xor_sync(0xffffffffu, p[j][1], off);
        }
    if (lane < 4) {
        #pragma unroll
        for (int j = 0; j < 4; j++) {
            int col = wn * 32 + j * 8 + lane * 2;
            part[wm * 128 + col]     = p[j][0];
            part[wm * 128 + col + 1] = p[j][1];
        }
    }
    __syncthreads();

    if (tid < 128) {
        float s = part[tid] + part[128 + tid] + part[256 + tid] + part[384 + tid];
        alpha[tid] = s;
        sred[tid]  = s;
    }
    __syncthreads();
    #pragma unroll
    for (int off = 64; off; off >>= 1) {
        if (tid < off) sred[tid] = fmaxf(sred[tid], sred[tid + off]);
        __syncthreads();
    }
    float mx = sred[0];
    __syncthreads();
    if (tid < 128) {
        float e = expf(alpha[tid] - mx);
        alpha[tid] = e;
        sred[tid]  = e;
    }
    __syncthreads();
    #pragma unroll
    for (int off = 64; off; off >>= 1) {
        if (tid < off) sred[tid] += sred[tid + off];
        __syncthreads();
    }
    float rsum = 1.0f / sred[0];
    __syncthreads();
    if (tid < 128) {
        float a = alpha[tid] * rsum;
        alpha[tid] = a;
        out[2 * B_ * GFS_ + src * B_ * NATOMS_ + b * NATOMS_ + tid] = a;
    }
    __syncthreads();

    // ---- vector[f] = sum_n alpha[n] * X[f][n] ----
    {
        int f = tid;
        const float4* xr = (const float4*)(X + (size_t)f * NATOMS_);
        const float4* al = (const float4*)alpha;
        float a = 0.0f;
        #pragma unroll 8
        for (int i = 0; i < 32; i++) {
            float4 v = xr[i];
            float4 w = al[i];
            a = fmaf(v.x, w.x, a);
            a = fmaf(v.y, w.y, a);
            a = fmaf(v.z, w.z, a);
            a = fmaf(v.w, w.w, a);
        }
        out[src * B_ * GFS_ + b * GFS_ + f] = a;
    }
}

// ---------------- launch ----------------
extern "C" void kernel_launch(void* const* d_in, const int* in_sizes, int n_in,
                              void* d_out, int out_size)
{
    const float* V  = (const float*)d_in[0];
    const float* Q  = (const float*)d_in[1];
    const float* Wm = (const float*)d_in[2];
    const float* Wv = (const float*)d_in[3];
    const float* Wq = (const float*)d_in[4];
    const float* Wh = (const float*)d_in[5];
    float* out = (float*)d_out;

    cudaFuncSetAttribute(main_kernel, cudaFuncAttributeMaxDynamicSharedMemorySize, SMEM_TOTAL);

    prep_kernel<<<256, 1024>>>(Wv, Wq);
    m0_kernel<<<B_ * 4, 256>>>(V, Q);
    gate_kernel<<<B_ / 4, 256>>>(Wm);
    dim3 grid(B_, 2);
    main_kernel<<<grid, 512, SMEM_TOTAL>>>(V, Q, Wh, out);
}

// round 5
// speedup vs baseline: 2.9916x; 1.4159x over previous
#include <cuda_runtime.h>
#include <cuda_bf16.h>
#include <cuda_fp16.h>
#include <cstdint>

#define B_      512
#define GFS_    512
#define NATOMS_ 128
#define KATT_   256

// ---------------- scratch (no cudaMalloc allowed) ----------------
__device__ float g_mgate[B_ * KATT_];
__device__ float g_M0[B_ * GFS_];
__device__ __half g_wHi[2][KATT_ * GFS_];   // W * 16, fp16 hi
__device__ __half g_wLo[2][KATT_ * GFS_];   // residual, fp16

// ---------------- helpers ----------------
__device__ __forceinline__ uint32_t smem_u32(const void* p) {
    uint32_t a;
    asm("{ .reg .u64 t; cvta.to.shared.u64 t, %1; cvt.u32.u64 %0, t; }" : "=r"(a) : "l"(p));
    return a;
}
__device__ __forceinline__ uint32_t sw128(uint32_t off) { return off ^ ((off >> 3) & 0x70); }

__device__ __forceinline__ void ldsm_x4(uint32_t* r, uint32_t addr) {
    asm volatile("ldmatrix.sync.aligned.m8n8.x4.shared.b16 {%0,%1,%2,%3}, [%4];"
                 : "=r"(r[0]), "=r"(r[1]), "=r"(r[2]), "=r"(r[3]) : "r"(addr));
}
__device__ __forceinline__ void mma_f16(float* c, const uint32_t* a, const uint32_t* b) {
    asm volatile("mma.sync.aligned.m16n8k16.row.col.f32.f16.f16.f32 "
                 "{%0,%1,%2,%3}, {%4,%5,%6,%7}, {%8,%9}, {%0,%1,%2,%3};"
                 : "+f"(c[0]), "+f"(c[1]), "+f"(c[2]), "+f"(c[3])
                 : "r"(a[0]), "r"(a[1]), "r"(a[2]), "r"(a[3]), "r"(b[0]), "r"(b[1]));
}
__device__ __forceinline__ void cp16(uint32_t saddr, const void* gaddr) {
    asm volatile("cp.async.cg.shared.global [%0], [%1], 16;" :: "r"(saddr), "l"(gaddr));
}
#define CP_COMMIT() asm volatile("cp.async.commit_group;" ::: "memory")
#define CP_WAIT0()  asm volatile("cp.async.wait_group 0;" ::: "memory")

// ---------------- branchless rational tanh (|err| ~1e-7) ----------------
__device__ __forceinline__ float rtanh(float x) {
    float xc = fminf(fmaxf(x, -7.9053111f), 7.9053111f);
    float s = xc * xc;
    float p = -2.76076847742355e-16f;
    p = fmaf(p, s,  2.00018790482477e-13f);
    p = fmaf(p, s, -8.60467152213735e-11f);
    p = fmaf(p, s,  5.12229709037114e-08f);
    p = fmaf(p, s,  1.48572235717979e-05f);
    p = fmaf(p, s,  6.37261928875436e-04f);
    p = fmaf(p, s,  4.89352455891786e-03f);
    p = p * xc;
    float q = 1.19825839466702e-06f;
    q = fmaf(q, s, 1.18534705686654e-04f);
    q = fmaf(q, s, 2.26843463243900e-03f);
    q = fmaf(q, s, 4.89352518554385e-03f);
    return __fdividef(p, q);
}

// ---------------- P0: W -> fp16 hi/lo (scaled x16 to keep lo normal) ----------------
__global__ __launch_bounds__(1024) void prep_kernel(const float* __restrict__ Wv,
                                                    const float* __restrict__ Wq)
{
    int id = blockIdx.x * 1024 + threadIdx.x;
    int src = id >> 17;
    int e   = id & 131071;
    float x = (src ? Wq : Wv)[e] * 16.0f;
    __half h = __float2half_rn(x);
    __half l = __float2half_rn(x - __half2float(h));
    g_wHi[src][e] = h;
    g_wLo[src][e] = l;
}

// ---------------- K1a: M0[b][f] = tanh(sumN V/64) * tanh(sumN Q/64) ----------------
__global__ __launch_bounds__(256) void m0_kernel(const float* __restrict__ V,
                                                 const float* __restrict__ Q)
{
    int b    = blockIdx.x >> 2;
    int part = blockIdx.x & 3;
    int lane = threadIdx.x & 31;
    int warp = threadIdx.x >> 5;

    for (int i = 0; i < 16; i++) {
        int f = part * 128 + warp * 16 + i;
        size_t base = ((size_t)b * GFS_ + f) * NATOMS_;
        float4 v = *(const float4*)(V + base + lane * 4);
        float4 q = *(const float4*)(Q + base + lane * 4);
        float sv = v.x + v.y + v.z + v.w;
        float sq = q.x + q.y + q.z + q.w;
        #pragma unroll
        for (int off = 16; off; off >>= 1) {
            sv += __shfl_xor_sync(0xffffffffu, sv, off);
            sq += __shfl_xor_sync(0xffffffffu, sq, off);
        }
        if (lane == 0)
            g_M0[b * GFS_ + f] = rtanh(sv * (1.0f / 64.0f)) * rtanh(sq * (1.0f / 64.0f));
    }
}

// ---------------- K1b: m_gate = tanh(Wm @ M0), 4 batches per CTA ----------------
__global__ __launch_bounds__(256) void gate_kernel(const float* __restrict__ Wm)
{
    __shared__ __align__(16) float M0s[4][GFS_];
    int b0  = blockIdx.x * 4;
    int tid = threadIdx.x;

    for (int i = tid; i < 4 * GFS_ / 4; i += 256)
        ((float4*)&M0s[0][0])[i] = ((const float4*)(g_M0 + b0 * GFS_))[i];
    __syncthreads();

    int k = tid;
    const float4* wr = (const float4*)(Wm + (size_t)k * GFS_);
    float acc0 = 0.f, acc1 = 0.f, acc2 = 0.f, acc3 = 0.f;
    #pragma unroll 4
    for (int i = 0; i < GFS_ / 4; i++) {
        float4 w = wr[i];
        float4 m0 = ((const float4*)M0s[0])[i];
        float4 m1 = ((const float4*)M0s[1])[i];
        float4 m2 = ((const float4*)M0s[2])[i];
        float4 m3 = ((const float4*)M0s[3])[i];
        acc0 = fmaf(w.x, m0.x, fmaf(w.y, m0.y, fmaf(w.z, m0.z, fmaf(w.w, m0.w, acc0))));
        acc1 = fmaf(w.x, m1.x, fmaf(w.y, m1.y, fmaf(w.z, m1.z, fmaf(w.w, m1.w, acc1))));
        acc2 = fmaf(w.x, m2.x, fmaf(w.y, m2.y, fmaf(w.z, m2.z, fmaf(w.w, m2.w, acc2))));
        acc3 = fmaf(w.x, m3.x, fmaf(w.y, m3.y, fmaf(w.z, m3.z, fmaf(w.w, m3.w, acc3))));
    }
    g_mgate[(b0 + 0) * KATT_ + k] = rtanh(acc0);
    g_mgate[(b0 + 1) * KATT_ + k] = rtanh(acc1);
    g_mgate[(b0 + 2) * KATT_ + k] = rtanh(acc2);
    g_mgate[(b0 + 3) * KATT_ + k] = rtanh(acc3);
}

// ---------------- K2: mma.sync fp16x2 main kernel ----------------
#define STAGE_BYTES 81920
#define A_HI_OFF    0
#define A_LO_OFF    32768
#define B_OFF       65536
#define WHG_OFF     163840
#define PART_OFF    164864
#define ALPHA_OFF   166912
#define SRED_OFF    167424
#define SMEM_TOTAL  167936

__device__ __forceinline__ void fillA(char* sm, uint32_t sb, int s, int f0, int tid,
                                      const __half* WHi, const __half* WLo)
{
    uint32_t stage = sb + s * STAGE_BYTES;
    #pragma unroll
    for (int it = 0; it < 4; it++) {
        int idx = it * 512 + tid;          // 0..2047
        int m   = idx >> 3;
        int cc  = idx & 7;
        uint32_t soff = sw128((uint32_t)(m * 128 + cc * 16));
        cp16(stage + A_HI_OFF + soff, WHi + (size_t)m * GFS_ + f0 + cc * 8);
        cp16(stage + A_LO_OFF + soff, WLo + (size_t)m * GFS_ + f0 + cc * 8);
    }
}

__device__ __forceinline__ void ldB(float* bx, const float* X, int f0, int tid)
{
    int nB = tid & 127;
    int fq = tid >> 7;
    #pragma unroll
    for (int j = 0; j < 4; j++) {
        int f = f0 + fq * 16 + j * 4;
        bx[j * 4 + 0] = X[(size_t)(f + 0) * NATOMS_ + nB];
        bx[j * 4 + 1] = X[(size_t)(f + 1) * NATOMS_ + nB];
        bx[j * 4 + 2] = X[(size_t)(f + 2) * NATOMS_ + nB];
        bx[j * 4 + 3] = X[(size_t)(f + 3) * NATOMS_ + nB];
    }
}

__device__ __forceinline__ void stB(char* sm, int s, const float* bx, int tid)
{
    int nB = tid & 127;
    int fq = tid >> 7;
    #pragma unroll
    for (int j = 0; j < 4; j++) {
        __half2 hA = __floats2half2_rn(bx[j*4+0], bx[j*4+1]);
        __half2 hB = __floats2half2_rn(bx[j*4+2], bx[j*4+3]);
        int fl = fq * 16 + j * 4;
        uint32_t soff = sw128((uint32_t)(nB * 128 + fl * 2));
        uint2 uh = { *(uint32_t*)&hA, *(uint32_t*)&hB };
        *(uint2*)(sm + s * STAGE_BYTES + B_OFF + soff) = uh;
    }
}

__global__ void __launch_bounds__(512, 1)
main_kernel(const float* __restrict__ V, const float* __restrict__ Q,
            const float* __restrict__ Wh, float* __restrict__ out)
{
    extern __shared__ char sm[];
    uint32_t sb = smem_u32(sm);

    int b   = blockIdx.x;
    int src = blockIdx.y;
    int tid = threadIdx.x;
    int wid = tid >> 5;
    int lane = tid & 31;

    const float* X = (src ? Q : V) + (size_t)b * GFS_ * NATOMS_;
    const __half* WHi = g_wHi[src];
    const __half* WLo = g_wLo[src];

    float* whg   = (float*)(sm + WHG_OFF);
    float* part  = (float*)(sm + PART_OFF);
    float* alpha = (float*)(sm + ALPHA_OFF);
    float* sred  = (float*)(sm + SRED_OFF);

    if (tid < KATT_) whg[tid] = Wh[tid] * g_mgate[b * KATT_ + tid];

    // warp tile: 64m x 32n;  4x4 warp grid
    int wm = wid >> 2;
    int wn = wid & 3;

    float acc[4][4][4];
    #pragma unroll
    for (int i = 0; i < 4; i++)
        #pragma unroll
        for (int j = 0; j < 4; j++)
            #pragma unroll
            for (int e = 0; e < 4; e++) acc[i][j][e] = 0.0f;

    uint32_t aRow = (uint32_t)((wm * 64 + (lane & 15)) * 128);
    uint32_t aCol = (uint32_t)((lane >> 4) * 16);
    uint32_t bRow = (uint32_t)((wn * 32 + ((lane >> 4) * 8) + (lane & 7)) * 128);
    uint32_t bCol = (uint32_t)(((lane >> 3) & 1) * 16);

    // prologue: fill chunk 0
    fillA(sm, sb, 0, 0, tid, WHi, WLo);
    CP_COMMIT();
    {
        float bx[16];
        ldB(bx, X, 0, tid);
        stB(sm, 0, bx, tid);
    }
    CP_WAIT0();
    __syncthreads();

    float bx[16];
    #pragma unroll 1
    for (int c = 0; c < 8; c++) {
        int s = c & 1;
        uint32_t stage = sb + s * STAGE_BYTES;

        if (c < 7) {
            fillA(sm, sb, s ^ 1, (c + 1) * 64, tid, WHi, WLo);
            CP_COMMIT();
            ldB(bx, X, (c + 1) * 64, tid);
        }

        uint32_t aHi = stage + A_HI_OFF;
        uint32_t aLo = stage + A_LO_OFF;
        uint32_t bB  = stage + B_OFF;

        #pragma unroll
        for (int ks = 0; ks < 4; ks++) {
            uint32_t kOff = (uint32_t)(ks * 32);
            uint32_t ah[4][4], al[4][4], bb[4][2];
            #pragma unroll
            for (int i = 0; i < 4; i++)
                ldsm_x4(ah[i], aHi + sw128(aRow + i * 2048 + kOff + aCol));
            #pragma unroll
            for (int jj = 0; jj < 2; jj++) {
                uint32_t r[4];
                ldsm_x4(r, bB + sw128(bRow + jj * 2048 + kOff + bCol));
                bb[2*jj][0]   = r[0]; bb[2*jj][1]   = r[1];
                bb[2*jj+1][0] = r[2]; bb[2*jj+1][1] = r[3];
            }
            #pragma unroll
            for (int i = 0; i < 4; i++)
                ldsm_x4(al[i], aLo + sw128(aRow + i * 2048 + kOff + aCol));
            #pragma unroll
            for (int i = 0; i < 4; i++)
                #pragma unroll
                for (int j = 0; j < 4; j++) {
                    mma_f16(acc[i][j], ah[i], bb[j]);   // hi product
                    mma_f16(acc[i][j], al[i], bb[j]);   // lo product
                }
        }

        if (c < 7) {
            stB(sm, s ^ 1, bx, tid);
            CP_WAIT0();
        }
        __syncthreads();
    }

    // ---- epilogue: col partials p[j][e] = sum_m whg[m]*tanh(T[m,n]/16) ----
    float p[4][2];
    #pragma unroll
    for (int j = 0; j < 4; j++) { p[j][0] = 0.f; p[j][1] = 0.f; }

    int m0r = wm * 64 + (lane >> 2);
    const float INV16 = 0.0625f;
    #pragma unroll
    for (int i = 0; i < 4; i++) {
        float w0 = whg[m0r + i * 16];
        float w1 = whg[m0r + i * 16 + 8];
        #pragma unroll
        for (int j = 0; j < 4; j++) {
            p[j][0] = fmaf(w0, rtanh(acc[i][j][0] * INV16), p[j][0]);
            p[j][1] = fmaf(w0, rtanh(acc[i][j][1] * INV16), p[j][1]);
            p[j][0] = fmaf(w1, rtanh(acc[i][j][2] * INV16), p[j][0]);
            p[j][1] = fmaf(w1, rtanh(acc[i][j][3] * INV16), p[j][1]);
        }
    }
    #pragma unroll
    for (int off = 4; off <= 16; off <<= 1)
        #pragma unroll
        for (int j = 0; j < 4; j++) {
            p[j][0] += __shfl_xor_sync(0xffffffffu, p[j][0], off);
            p[j][1] += __shfl_xor_sync(0xffffffffu, p[j][1], off);
        }
    if (lane < 4) {
        #pragma unroll
        for (int j = 0; j < 4; j++) {
            int col = wn * 32 + j * 8 + lane * 2;
            part[wm * 128 + col]     = p[j][0];
            part[wm * 128 + col + 1] = p[j][1];
        }
    }
    __syncthreads();

    if (tid < 128) {
        float s = part[tid] + part[128 + tid] + part[256 + tid] + part[384 + tid];
        alpha[tid] = s;
        sred[tid]  = s;
    }
    __syncthreads();
    #pragma unroll
    for (int off = 64; off; off >>= 1) {
        if (tid < off) sred[tid] = fmaxf(sred[tid], sred[tid + off]);
        __syncthreads();
    }
    float mx = sred[0];
    __syncthreads();
    if (tid < 128) {
        float e = expf(alpha[tid] - mx);
        alpha[tid] = e;
        sred[tid]  = e;
    }
    __syncthreads();
    #pragma unroll
    for (int off = 64; off; off >>= 1) {
        if (tid < off) sred[tid] += sred[tid + off];
        __syncthreads();
    }
    float rsum = 1.0f / sred[0];
    __syncthreads();
    if (tid < 128) {
        float a = alpha[tid] * rsum;
        alpha[tid] = a;
        out[2 * B_ * GFS_ + src * B_ * NATOMS_ + b * NATOMS_ + tid] = a;
    }
    __syncthreads();

    // ---- vector[f] = sum_n alpha[n] * X[f][n] ----
    {
        int f = tid;
        const float4* xr = (const float4*)(X + (size_t)f * NATOMS_);
        const float4* al = (const float4*)alpha;
        float a = 0.0f;
        #pragma unroll 8
        for (int i = 0; i < 32; i++) {
            float4 v = xr[i];
            float4 w = al[i];
            a = fmaf(v.x, w.x, a);
            a = fmaf(v.y, w.y, a);
            a = fmaf(v.z, w.z, a);
            a = fmaf(v.w, w.w, a);
        }
        out[src * B_ * GFS_ + b * GFS_ + f] = a;
    }
}

// ---------------- launch ----------------
extern "C" void kernel_launch(void* const* d_in, const int* in_sizes, int n_in,
                              void* d_out, int out_size)
{
    const float* V  = (const float*)d_in[0];
    const float* Q  = (const float*)d_in[1];
    const float* Wm = (const float*)d_in[2];
    const float* Wv = (const float*)d_in[3];
    const float* Wq = (const float*)d_in[4];
    const float* Wh = (const float*)d_in[5];
    float* out = (float*)d_out;

    cudaFuncSetAttribute(main_kernel, cudaFuncAttributeMaxDynamicSharedMemorySize, SMEM_TOTAL);

    prep_kernel<<<256, 1024>>>(Wv, Wq);
    m0_kernel<<<B_ * 4, 256>>>(V, Q);
    gate_kernel<<<B_ / 4, 256>>>(Wm);
    dim3 grid(B_, 2);
    main_kernel<<<grid, 512, SMEM_TOTAL>>>(V, Q, Wh, out);
}

// round 6
// speedup vs baseline: 4.3445x; 1.4522x over previous
#include <cuda_runtime.h>
#include <cuda_bf16.h>
#include <cuda_fp16.h>
#include <cstdint>

#define B_      512
#define GFS_    512
#define NATOMS_ 128
#define KATT_   256

// ---------------- scratch (no cudaMalloc allowed) ----------------
__device__ float g_mgate[B_ * KATT_];
__device__ float g_M0[B_ * GFS_];
__device__ __half g_w16[2][KATT_ * GFS_];                    // W fp16
__device__ __half g_X16[2][(size_t)B_ * GFS_ * NATOMS_];     // X fp16, [b][f][n]

// ---------------- helpers ----------------
__device__ __forceinline__ uint32_t smem_u32(const void* p) {
    uint32_t a;
    asm("{ .reg .u64 t; cvta.to.shared.u64 t, %1; cvt.u32.u64 %0, t; }" : "=r"(a) : "l"(p));
    return a;
}
__device__ __forceinline__ uint32_t sw128(uint32_t off) { return off ^ ((off >> 3) & 0x70); }

__device__ __forceinline__ void ldsm_x4(uint32_t* r, uint32_t addr) {
    asm volatile("ldmatrix.sync.aligned.m8n8.x4.shared.b16 {%0,%1,%2,%3}, [%4];"
                 : "=r"(r[0]), "=r"(r[1]), "=r"(r[2]), "=r"(r[3]) : "r"(addr));
}
__device__ __forceinline__ void ldsm_x4t(uint32_t* r, uint32_t addr) {
    asm volatile("ldmatrix.sync.aligned.m8n8.x4.trans.shared.b16 {%0,%1,%2,%3}, [%4];"
                 : "=r"(r[0]), "=r"(r[1]), "=r"(r[2]), "=r"(r[3]) : "r"(addr));
}
__device__ __forceinline__ void mma_f16(float* c, const uint32_t* a, const uint32_t* b) {
    asm volatile("mma.sync.aligned.m16n8k16.row.col.f32.f16.f16.f32 "
                 "{%0,%1,%2,%3}, {%4,%5,%6,%7}, {%8,%9}, {%0,%1,%2,%3};"
                 : "+f"(c[0]), "+f"(c[1]), "+f"(c[2]), "+f"(c[3])
                 : "r"(a[0]), "r"(a[1]), "r"(a[2]), "r"(a[3]), "r"(b[0]), "r"(b[1]));
}
__device__ __forceinline__ void cp16(uint32_t saddr, const void* gaddr) {
    asm volatile("cp.async.cg.shared.global [%0], [%1], 16;" :: "r"(saddr), "l"(gaddr));
}
#define CP_COMMIT() asm volatile("cp.async.commit_group;" ::: "memory")
#define CP_WAIT0()  asm volatile("cp.async.wait_group 0;" ::: "memory")
#define CP_WAIT1()  asm volatile("cp.async.wait_group 1;" ::: "memory")

// ---------------- branchless rational tanh (|err| ~1e-7) ----------------
__device__ __forceinline__ float rtanh(float x) {
    float xc = fminf(fmaxf(x, -7.9053111f), 7.9053111f);
    float s = xc * xc;
    float p = -2.76076847742355e-16f;
    p = fmaf(p, s,  2.00018790482477e-13f);
    p = fmaf(p, s, -8.60467152213735e-11f);
    p = fmaf(p, s,  5.12229709037114e-08f);
    p = fmaf(p, s,  1.48572235717979e-05f);
    p = fmaf(p, s,  6.37261928875436e-04f);
    p = fmaf(p, s,  4.89352455891786e-03f);
    p = p * xc;
    float q = 1.19825839466702e-06f;
    q = fmaf(q, s, 1.18534705686654e-04f);
    q = fmaf(q, s, 2.26843463243900e-03f);
    q = fmaf(q, s, 4.89352518554385e-03f);
    return __fdividef(p, q);
}

// ---------------- P0: W -> fp16 ----------------
__global__ __launch_bounds__(1024) void prep_kernel(const float* __restrict__ Wv,
                                                    const float* __restrict__ Wq)
{
    int id = blockIdx.x * 1024 + threadIdx.x;
    int src = id >> 17;
    int e   = id & 131071;
    g_w16[src][e] = __float2half_rn((src ? Wq : Wv)[e]);
}

// ---------------- K1a: rowsums -> M0; also write X fp16 copy ----------------
__global__ __launch_bounds__(256) void m0_kernel(const float* __restrict__ V,
                                                 const float* __restrict__ Q)
{
    int b    = blockIdx.x >> 2;
    int part = blockIdx.x & 3;
    int lane = threadIdx.x & 31;
    int warp = threadIdx.x >> 5;

    for (int i = 0; i < 16; i++) {
        int f = part * 128 + warp * 16 + i;
        size_t base = ((size_t)b * GFS_ + f) * NATOMS_;
        float4 v = *(const float4*)(V + base + lane * 4);
        float4 q = *(const float4*)(Q + base + lane * 4);

        // fp16 copies (coalesced 8B per lane)
        __half2 vh0 = __floats2half2_rn(v.x, v.y);
        __half2 vh1 = __floats2half2_rn(v.z, v.w);
        __half2 qh0 = __floats2half2_rn(q.x, q.y);
        __half2 qh1 = __floats2half2_rn(q.z, q.w);
        uint2 vu = { *(uint32_t*)&vh0, *(uint32_t*)&vh1 };
        uint2 qu = { *(uint32_t*)&qh0, *(uint32_t*)&qh1 };
        *(uint2*)(&g_X16[0][base + lane * 4]) = vu;
        *(uint2*)(&g_X16[1][base + lane * 4]) = qu;

        float sv = v.x + v.y + v.z + v.w;
        float sq = q.x + q.y + q.z + q.w;
        #pragma unroll
        for (int off = 16; off; off >>= 1) {
            sv += __shfl_xor_sync(0xffffffffu, sv, off);
            sq += __shfl_xor_sync(0xffffffffu, sq, off);
        }
        if (lane == 0)
            g_M0[b * GFS_ + f] = rtanh(sv * (1.0f / 64.0f)) * rtanh(sq * (1.0f / 64.0f));
    }
}

// ---------------- K1b: m_gate = tanh(Wm @ M0), 4 batches per CTA ----------------
__global__ __launch_bounds__(256) void gate_kernel(const float* __restrict__ Wm)
{
    __shared__ __align__(16) float M0s[4][GFS_];
    int b0  = blockIdx.x * 4;
    int tid = threadIdx.x;

    for (int i = tid; i < 4 * GFS_ / 4; i += 256)
        ((float4*)&M0s[0][0])[i] = ((const float4*)(g_M0 + b0 * GFS_))[i];
    __syncthreads();

    int k = tid;
    const float4* wr = (const float4*)(Wm + (size_t)k * GFS_);
    float acc0 = 0.f, acc1 = 0.f, acc2 = 0.f, acc3 = 0.f;
    #pragma unroll 4
    for (int i = 0; i < GFS_ / 4; i++) {
        float4 w = wr[i];
        float4 m0 = ((const float4*)M0s[0])[i];
        float4 m1 = ((const float4*)M0s[1])[i];
        float4 m2 = ((const float4*)M0s[2])[i];
        float4 m3 = ((const float4*)M0s[3])[i];
        acc0 = fmaf(w.x, m0.x, fmaf(w.y, m0.y, fmaf(w.z, m0.z, fmaf(w.w, m0.w, acc0))));
        acc1 = fmaf(w.x, m1.x, fmaf(w.y, m1.y, fmaf(w.z, m1.z, fmaf(w.w, m1.w, acc1))));
        acc2 = fmaf(w.x, m2.x, fmaf(w.y, m2.y, fmaf(w.z, m2.z, fmaf(w.w, m2.w, acc2))));
        acc3 = fmaf(w.x, m3.x, fmaf(w.y, m3.y, fmaf(w.z, m3.z, fmaf(w.w, m3.w, acc3))));
    }
    g_mgate[(b0 + 0) * KATT_ + k] = rtanh(acc0);
    g_mgate[(b0 + 1) * KATT_ + k] = rtanh(acc1);
    g_mgate[(b0 + 2) * KATT_ + k] = rtanh(acc2);
    g_mgate[(b0 + 3) * KATT_ + k] = rtanh(acc3);
}

// ---------------- K2: mma.sync fp16 single-product, 3-stage cp.async ----------------
#define A_OFF       0
#define B_OFF       32768
#define STAGE_BYTES 49152
#define WHG_OFF     147456
#define PART_OFF    148480
#define ALPHA_OFF   150528
#define SRED_OFF    151040
#define SMEM_TOTAL  151552

// A chunk [256 m][64 f] fp16 SW128 (rows 128B)
__device__ __forceinline__ void fillA(uint32_t sb, int s, int f0, int tid, const __half* W16)
{
    uint32_t stage = sb + s * STAGE_BYTES + A_OFF;
    #pragma unroll
    for (int it = 0; it < 4; it++) {
        int idx = it * 512 + tid;          // 0..2047
        int m   = idx >> 3;
        int u   = idx & 7;
        cp16(stage + sw128((uint32_t)(m * 128 + u * 16)),
             W16 + (size_t)m * GFS_ + f0 + u * 8);
    }
}

// B chunk [64 k(f)][128 n] fp16, rows 256B, 16B-unit XOR by (k&7)
__device__ __forceinline__ void fillB(uint32_t sb, int s, int f0, int tid, const __half* Xrow)
{
    uint32_t stage = sb + s * STAGE_BYTES + B_OFF;
    #pragma unroll
    for (int it = 0; it < 2; it++) {
        int idx = it * 512 + tid;          // 0..1023
        int k   = idx >> 4;
        int u   = idx & 15;
        cp16(stage + (uint32_t)(k * 256 + ((u << 4) ^ ((k & 7) << 4))),
             Xrow + (size_t)(f0 + k) * NATOMS_ + u * 8);
    }
}

__global__ void __launch_bounds__(512, 1)
main_kernel(const float* __restrict__ Wh, float* __restrict__ out)
{
    extern __shared__ char sm[];
    uint32_t sb = smem_u32(sm);

    int b   = blockIdx.x;
    int src = blockIdx.y;
    int tid = threadIdx.x;
    int wid = tid >> 5;
    int lane = tid & 31;

    const __half* W16  = g_w16[src];
    const __half* Xrow = g_X16[src] + (size_t)b * GFS_ * NATOMS_;

    float* whg   = (float*)(sm + WHG_OFF);
    float* part  = (float*)(sm + PART_OFF);
    float* alpha = (float*)(sm + ALPHA_OFF);
    float* sred  = (float*)(sm + SRED_OFF);

    if (tid < KATT_) whg[tid] = Wh[tid] * g_mgate[b * KATT_ + tid];

    // warp tile: 64m x 32n; 4x4 warp grid
    int wm = wid >> 2;
    int wn = wid & 3;

    float acc[4][4][4];
    #pragma unroll
    for (int i = 0; i < 4; i++)
        #pragma unroll
        for (int j = 0; j < 4; j++)
            #pragma unroll
            for (int e = 0; e < 4; e++) acc[i][j][e] = 0.0f;

    // A ldsm addressing (as R5)
    uint32_t aRow = (uint32_t)((wm * 64 + (lane & 15)) * 128);
    uint32_t aCol = (uint32_t)((lane >> 4) * 16);
    // B ldsm.trans addressing: lane -> (q, r)
    int q = lane >> 3;
    int r = lane & 7;
    uint32_t bKpart = (uint32_t)((q & 1) * 8 + r);   // row within kstep
    uint32_t bUpart = (uint32_t)(wn * 4 + (q >> 1)); // 16B-unit base (+ jj*2)

    // prologue: fill stages 0,1
    fillA(sb, 0, 0, tid, W16);
    fillB(sb, 0, 0, tid, Xrow);
    CP_COMMIT();
    fillA(sb, 1, 64, tid, W16);
    fillB(sb, 1, 64, tid, Xrow);
    CP_COMMIT();
    CP_WAIT1();
    __syncthreads();

    #pragma unroll
    for (int c = 0; c < 8; c++) {
        int s = c % 3;
        uint32_t stage = sb + s * STAGE_BYTES;

        if (c + 2 < 8) {
            int sn = (c + 2) % 3;
            fillA(sb, sn, (c + 2) * 64, tid, W16);
            fillB(sb, sn, (c + 2) * 64, tid, Xrow);
            CP_COMMIT();
        }

        uint32_t aB = stage + A_OFF;
        uint32_t bB = stage + B_OFF;

        #pragma unroll
        for (int ks = 0; ks < 4; ks++) {
            uint32_t kOff = (uint32_t)(ks * 32);
            uint32_t a[4][4], bb[4][2];
            #pragma unroll
            for (int i = 0; i < 4; i++)
                ldsm_x4(a[i], aB + sw128(aRow + i * 2048 + kOff + aCol));
            #pragma unroll
            for (int jj = 0; jj < 2; jj++) {
                uint32_t kRow = ks * 16 + bKpart;
                uint32_t un   = bUpart + jj * 2;
                uint32_t addr = bB + kRow * 256 + ((un * 16) ^ ((kRow & 7) * 16));
                uint32_t rr[4];
                ldsm_x4t(rr, addr);
                bb[2*jj][0]   = rr[0]; bb[2*jj][1]   = rr[1];
                bb[2*jj+1][0] = rr[2]; bb[2*jj+1][1] = rr[3];
            }
            #pragma unroll
            for (int i = 0; i < 4; i++)
                #pragma unroll
                for (int j = 0; j < 4; j++)
                    mma_f16(acc[i][j], a[i], bb[j]);
        }

        if (c < 6) CP_WAIT1(); else CP_WAIT0();
        __syncthreads();
    }

    // ---- epilogue: col partials p[j][e] = sum_m whg[m]*tanh(T[m,n]) ----
    float p[4][2];
    #pragma unroll
    for (int j = 0; j < 4; j++) { p[j][0] = 0.f; p[j][1] = 0.f; }

    int m0r = wm * 64 + (lane >> 2);
    #pragma unroll
    for (int i = 0; i < 4; i++) {
        float w0 = whg[m0r + i * 16];
        float w1 = whg[m0r + i * 16 + 8];
        #pragma unroll
        for (int j = 0; j < 4; j++) {
            p[j][0] = fmaf(w0, rtanh(acc[i][j][0]), p[j][0]);
            p[j][1] = fmaf(w0, rtanh(acc[i][j][1]), p[j][1]);
            p[j][0] = fmaf(w1, rtanh(acc[i][j][2]), p[j][0]);
            p[j][1] = fmaf(w1, rtanh(acc[i][j][3]), p[j][1]);
        }
    }
    #pragma unroll
    for (int off = 4; off <= 16; off <<= 1)
        #pragma unroll
        for (int j = 0; j < 4; j++) {
            p[j][0] += __shfl_xor_sync(0xffffffffu, p[j][0], off);
            p[j][1] += __shfl_xor_sync(0xffffffffu, p[j][1], off);
        }
    if (lane < 4) {
        #pragma unroll
        for (int j = 0; j < 4; j++) {
            int col = wn * 32 + j * 8 + lane * 2;
            part[wm * 128 + col]     = p[j][0];
            part[wm * 128 + col + 1] = p[j][1];
        }
    }
    __syncthreads();

    if (tid < 128) {
        float s = part[tid] + part[128 + tid] + part[256 + tid] + part[384 + tid];
        alpha[tid] = s;
        sred[tid]  = s;
    }
    __syncthreads();
    #pragma unroll
    for (int off = 64; off; off >>= 1) {
        if (tid < off) sred[tid] = fmaxf(sred[tid], sred[tid + off]);
        __syncthreads();
    }
    float mx = sred[0];
    __syncthreads();
    if (tid < 128) {
        float e = expf(alpha[tid] - mx);
        alpha[tid] = e;
        sred[tid]  = e;
    }
    __syncthreads();
    #pragma unroll
    for (int off = 64; off; off >>= 1) {
        if (tid < off) sred[tid] += sred[tid + off];
        __syncthreads();
    }
    float rsum = 1.0f / sred[0];
    __syncthreads();
    if (tid < 128) {
        float a = alpha[tid] * rsum;
        alpha[tid] = a;
        out[2 * B_ * GFS_ + src * B_ * NATOMS_ + b * NATOMS_ + tid] = a;
    }
    __syncthreads();

    // ---- vector[f] = sum_n alpha[n] * X16[f][n]  (L2-hot) ----
    {
        int f = tid;
        const uint4* xr = (const uint4*)(Xrow + (size_t)f * NATOMS_);
        float a = 0.0f;
        #pragma unroll
        for (int i = 0; i < 16; i++) {
            uint4 u = xr[i];
            const float* al = alpha + i * 8;
            float2 p0 = __half22float2(*(const __half2*)&u.x);
            float2 p1 = __half22float2(*(const __half2*)&u.y);
            float2 p2 = __half22float2(*(const __half2*)&u.z);
            float2 p3 = __half22float2(*(const __half2*)&u.w);
            a = fmaf(p0.x, al[0], a); a = fmaf(p0.y, al[1], a);
            a = fmaf(p1.x, al[2], a); a = fmaf(p1.y, al[3], a);
            a = fmaf(p2.x, al[4], a); a = fmaf(p2.y, al[5], a);
            a = fmaf(p3.x, al[6], a); a = fmaf(p3.y, al[7], a);
        }
        out[src * B_ * GFS_ + b * GFS_ + f] = a;
    }
}

// ---------------- launch ----------------
extern "C" void kernel_launch(void* const* d_in, const int* in_sizes, int n_in,
                              void* d_out, int out_size)
{
    const float* V  = (const float*)d_in[0];
    const float* Q  = (const float*)d_in[1];
    const float* Wm = (const float*)d_in[2];
    const float* Wv = (const float*)d_in[3];
    const float* Wq = (const float*)d_in[4];
    const float* Wh = (const float*)d_in[5];
    float* out = (float*)d_out;

    cudaFuncSetAttribute(main_kernel, cudaFuncAttributeMaxDynamicSharedMemorySize, SMEM_TOTAL);

    prep_kernel<<<256, 1024>>>(Wv, Wq);
    m0_kernel<<<B_ * 4, 256>>>(V, Q);
    gate_kernel<<<B_ / 4, 256>>>(Wm);
    dim3 grid(B_, 2);
    main_kernel<<<grid, 512, SMEM_TOTAL>>>(Wh, out);
}